// round 6
// baseline (speedup 1.0000x reference)
#include <cuda_runtime.h>
#include <cuda_fp16.h>
#include <math.h>
#include <stdint.h>

#define NN 50000
#define EE 800000
#define KDIM 128
#define HID 128
#define CLS 40

#define ALD 68   // half2-words per smem row (64 data + 4 pad); 68 % 32 == 4 -> conflict-free MMA frag loads

// ---------------- scratch (device globals; no allocation allowed) ----------------
__device__ int   g_deg_out[NN];
__device__ int   g_deg_in[NN];
__device__ int   g_cursor[NN];
__device__ int   g_row_ptr[NN + 1];
__device__ int   g_col[EE];
__device__ float g_norm_out[NN];
__device__ float g_norm_in[NN];
__device__ int   g_block_sums[256];
__device__ int   g_block_off[256];
__device__ __align__(16) uint32_t g_wt0[128 * ALD];   // W0^T fp16, n-major k-contig
__device__ __align__(16) uint32_t g_wt1[128 * ALD];   // W1^T
__device__ __align__(16) uint32_t g_wt2[40 * ALD];    // W2^T
__device__ __align__(16) float g_buf_a[(size_t)NN * 128];   // fp16 scratch
__device__ __align__(16) float g_buf_b[(size_t)NN * 128];   // fp16 scratch

// ---------------- graph preprocessing ----------------
__global__ void init_zero_kernel(int n) {
    for (int i = blockIdx.x * blockDim.x + threadIdx.x; i < n; i += gridDim.x * blockDim.x) {
        g_deg_out[i] = 0;
        g_deg_in[i]  = 0;
    }
}

__global__ void degree_kernel(const int* __restrict__ src, const int* __restrict__ dst, int E) {
    int e = blockIdx.x * blockDim.x + threadIdx.x;
    if (e < E) {
        atomicAdd(&g_deg_out[src[e]], 1);
        atomicAdd(&g_deg_in[dst[e]], 1);
    }
}

__global__ void norm_partial_kernel(int n) {
    __shared__ int sdata[8];
    int t = threadIdx.x;
    int i = blockIdx.x * 256 + t;
    int din = 0;
    if (i < n) {
        int dout = g_deg_out[i]; if (dout < 1) dout = 1;
        din = g_deg_in[i];
        int dc = (din < 1) ? 1 : din;
        g_norm_out[i] = rsqrtf((float)dout);
        g_norm_in[i]  = rsqrtf((float)dc);
    }
    int v = din;
    for (int off = 16; off > 0; off >>= 1)
        v += __shfl_down_sync(0xffffffff, v, off);
    if ((t & 31) == 0) sdata[t >> 5] = v;
    __syncthreads();
    if (t < 8) {
        int w = sdata[t];
        for (int off = 4; off > 0; off >>= 1)
            w += __shfl_down_sync(0xff, w, off);
        if (t == 0) g_block_sums[blockIdx.x] = w;
    }
}

__global__ void scan_offsets_kernel(int nblocks, int n) {
    __shared__ int s[256];
    int t = threadIdx.x;
    int v = (t < nblocks) ? g_block_sums[t] : 0;
    s[t] = v;
    __syncthreads();
    for (int off = 1; off < 256; off <<= 1) {
        int u = (t >= off) ? s[t - off] : 0;
        __syncthreads();
        s[t] += u;
        __syncthreads();
    }
    if (t < nblocks) g_block_off[t] = s[t] - v;
    if (t == nblocks - 1) g_row_ptr[n] = s[t];
}

__global__ void fill_rowptr_kernel(int n) {
    __shared__ int s[256];
    int t = threadIdx.x;
    int i = blockIdx.x * 256 + t;
    int v = (i < n) ? g_deg_in[i] : 0;
    s[t] = v;
    __syncthreads();
    for (int off = 1; off < 256; off <<= 1) {
        int u = (t >= off) ? s[t - off] : 0;
        __syncthreads();
        s[t] += u;
        __syncthreads();
    }
    if (i < n) {
        int rp = s[t] - v + g_block_off[blockIdx.x];
        g_row_ptr[i] = rp;
        g_cursor[i]  = rp;
    }
}

__global__ void csr_fill_kernel(const int* __restrict__ src, const int* __restrict__ dst, int E) {
    int e = blockIdx.x * blockDim.x + threadIdx.x;
    if (e < E) {
        int p = atomicAdd(&g_cursor[dst[e]], 1);
        g_col[p] = src[e];
    }
}

// ---------------- weight pre-conversion: W (KxN fp32 row-major) -> WT (n-major, k-contig fp16) ----------------
// WT word (n*ALD + j) packs halves (W[2j][n] lo, W[2j+1][n] hi)  -- matches verified round-5 fragment layout
__global__ void wconvert128_kernel(const float* __restrict__ W, uint32_t* __restrict__ WT) {
    int li = blockIdx.x * 256 + threadIdx.x;   // 8192 tasks
    int n = li & 127;
    int j = li >> 7;                           // 0..63
    float lo = W[(size_t)(2 * j) * 128 + n];
    float hi = W[(size_t)(2 * j + 1) * 128 + n];
    __half2 h = __float22half2_rn(make_float2(lo, hi));
    WT[n * ALD + j] = *(uint32_t*)&h;
}

__global__ void wconvert40_kernel(const float* __restrict__ W, uint32_t* __restrict__ WT) {
    int li = blockIdx.x * 256 + threadIdx.x;   // 2560 tasks
    if (li >= 40 * 64) return;
    int n = li % 40;
    int j = li / 40;                           // 0..63
    float lo = W[(size_t)(2 * j) * CLS + n];
    float hi = W[(size_t)(2 * j + 1) * CLS + n];
    __half2 h = __float22half2_rn(make_float2(lo, hi));
    WT[n * ALD + j] = *(uint32_t*)&h;
}

// ---------------- MMA macro (fp16 inputs, fp32 accum) ----------------
#define MMA_H16(d, a, b)                                                     \
    asm volatile(                                                            \
        "mma.sync.aligned.m16n8k16.row.col.f32.f16.f16.f32 "                 \
        "{%0,%1,%2,%3}, {%4,%5,%6,%7}, {%8,%9}, {%0,%1,%2,%3};"              \
        : "+f"(d[0]), "+f"(d[1]), "+f"(d[2]), "+f"(d[3])                     \
        : "r"(a[0]), "r"(a[1]), "r"(a[2]), "r"(a[3]), "r"(b[0]), "r"(b[1]))

#define GEMM_SMEM  ((128 * ALD + 128 * ALD) * 4)
#define GEMM40_SMEM ((128 * ALD + 40 * ALD) * 4)

// ---------------- layer-0 GEMM: fp32 features -> fp16 features@W0 ----------------
__global__ void __launch_bounds__(256)
gemm0_kernel(const float* __restrict__ A, const uint4* __restrict__ WT /* 17 uint4/row */,
             uint32_t* __restrict__ out /* 64 half2 words/row */, int M) {
    extern __shared__ uint32_t sm[];
    uint32_t* As = sm;                 // [128][ALD]
    uint32_t* Ws = sm + 128 * ALD;     // [128][ALD]

    int tid = threadIdx.x, warp = tid >> 5, lane = tid & 31;
    int rowBase = blockIdx.x * 128;

    // copy preconverted W0^T (128 rows x 16 uint4)
#pragma unroll
    for (int it = 0; it < 8; it++) {
        int li = it * 256 + tid;
        int n  = li >> 4;
        int q  = li & 15;
        uint4 v = WT[n * 17 + q];
        uint32_t* p = Ws + n * ALD + q * 4;
        p[0] = v.x; p[1] = v.y; p[2] = v.z; p[3] = v.w;
    }
    // load + convert fp32 A
#pragma unroll
    for (int it = 0; it < 16; it++) {
        int li = it * 256 + tid;
        int r  = li >> 5;
        int c4 = (li & 31) << 2;
        float4 v = make_float4(0.f, 0.f, 0.f, 0.f);
        if (rowBase + r < M)
            v = *(const float4*)(A + (size_t)(rowBase + r) * 128 + c4);
        ((__half2*)As)[r * ALD + (c4 >> 1)]     = __float22half2_rn(make_float2(v.x, v.y));
        ((__half2*)As)[r * ALD + (c4 >> 1) + 1] = __float22half2_rn(make_float2(v.z, v.w));
    }
    __syncthreads();

    int warpRow = warp >> 2, warpCol = warp & 3;
    int gid = lane >> 2, tig = lane & 3;
    int aBase = warpRow * 64, bBase = warpCol * 32;

    float acc[4][4][4];
#pragma unroll
    for (int mf = 0; mf < 4; mf++)
#pragma unroll
        for (int nf = 0; nf < 4; nf++)
#pragma unroll
            for (int q = 0; q < 4; q++) acc[mf][nf][q] = 0.f;

#pragma unroll
    for (int ks = 0; ks < 8; ks++) {
        int kw = ks * 8;
        uint32_t bfr[4][2];
#pragma unroll
        for (int nf = 0; nf < 4; nf++) {
            int n = bBase + nf * 8 + gid;
            bfr[nf][0] = Ws[n * ALD + kw + tig];
            bfr[nf][1] = Ws[n * ALD + kw + 4 + tig];
        }
        uint32_t afr[4][4];
#pragma unroll
        for (int mf = 0; mf < 4; mf++) {
            int r = aBase + mf * 16 + gid;
            afr[mf][0] = As[r * ALD + kw + tig];
            afr[mf][1] = As[(r + 8) * ALD + kw + tig];
            afr[mf][2] = As[r * ALD + kw + 4 + tig];
            afr[mf][3] = As[(r + 8) * ALD + kw + 4 + tig];
        }
#pragma unroll
        for (int mf = 0; mf < 4; mf++)
#pragma unroll
            for (int nf = 0; nf < 4; nf++)
                MMA_H16(acc[mf][nf], afr[mf], bfr[nf]);
    }

#pragma unroll
    for (int mf = 0; mf < 4; mf++) {
        int r0 = rowBase + aBase + mf * 16 + gid;
        int r1 = r0 + 8;
#pragma unroll
        for (int nf = 0; nf < 4; nf++) {
            int h2col = ((bBase + nf * 8) >> 1) + tig;
            if (r0 < M)
                ((__half2*)out)[(size_t)r0 * 64 + h2col] =
                    __float22half2_rn(make_float2(acc[mf][nf][0], acc[mf][nf][1]));
            if (r1 < M)
                ((__half2*)out)[(size_t)r1 * 64 + h2col] =
                    __float22half2_rn(make_float2(acc[mf][nf][2], acc[mf][nf][3]));
        }
    }
}

// ---------------- fused aggregation + GEMM (128 out cols) ----------------
// agg: h[r] = relu(norm_in[r]*sum_e w_e*gin[src_e] + bias) * norm_out[r]  -> smem As -> @ WT -> out fp16
template <int EW>
__global__ void __launch_bounds__(256)
fused_agg_gemm128(const uint32_t* __restrict__ gin /* 64 half2 words/row */,
                  const uint4* __restrict__ WT,
                  const float* __restrict__ bias,
                  uint32_t* __restrict__ out, int M) {
    extern __shared__ uint32_t sm[];
    uint32_t* As = sm;
    uint32_t* Ws = sm + 128 * ALD;

    int tid = threadIdx.x, warp = tid >> 5, lane = tid & 31;
    int rowBase = blockIdx.x * 128;

    // copy W^T
#pragma unroll
    for (int it = 0; it < 8; it++) {
        int li = it * 256 + tid;
        int n  = li >> 4;
        int q  = li & 15;
        uint4 v = WT[n * 17 + q];
        uint32_t* p = Ws + n * ALD + q * 4;
        p[0] = v.x; p[1] = v.y; p[2] = v.z; p[3] = v.w;
    }

    // ---- aggregation phase ----
    int c  = tid & 63;
    int ty = tid >> 6;
    float2 bc = *(const float2*)(bias + 2 * c);
#pragma unroll 1
    for (int rr = 0; rr < 32; rr++) {
        int r = ty * 32 + rr;
        int node = rowBase + r;
        if (node < M) {
            int beg = g_row_ptr[node];
            int end = g_row_ptr[node + 1];
            float ax = 0.f, ay = 0.f;
            int e = beg;
            for (; e + 3 < end; e += 4) {
                int s0 = g_col[e], s1 = g_col[e + 1], s2 = g_col[e + 2], s3 = g_col[e + 3];
                uint32_t u0 = gin[(size_t)s0 * 64 + c];
                uint32_t u1 = gin[(size_t)s1 * 64 + c];
                uint32_t u2 = gin[(size_t)s2 * 64 + c];
                uint32_t u3 = gin[(size_t)s3 * 64 + c];
                float2 f0 = __half22float2(*(__half2*)&u0);
                float2 f1 = __half22float2(*(__half2*)&u1);
                float2 f2 = __half22float2(*(__half2*)&u2);
                float2 f3 = __half22float2(*(__half2*)&u3);
                if (EW) {
                    float w0 = g_norm_out[s0], w1 = g_norm_out[s1];
                    float w2 = g_norm_out[s2], w3 = g_norm_out[s3];
                    ax = fmaf(f0.x, w0, ax); ay = fmaf(f0.y, w0, ay);
                    ax = fmaf(f1.x, w1, ax); ay = fmaf(f1.y, w1, ay);
                    ax = fmaf(f2.x, w2, ax); ay = fmaf(f2.y, w2, ay);
                    ax = fmaf(f3.x, w3, ax); ay = fmaf(f3.y, w3, ay);
                } else {
                    ax += f0.x + f1.x + f2.x + f3.x;
                    ay += f0.y + f1.y + f2.y + f3.y;
                }
            }
            for (; e < end; e++) {
                int s0 = g_col[e];
                uint32_t u0 = gin[(size_t)s0 * 64 + c];
                float2 f0 = __half22float2(*(__half2*)&u0);
                if (EW) {
                    float w0 = g_norm_out[s0];
                    ax = fmaf(f0.x, w0, ax); ay = fmaf(f0.y, w0, ay);
                } else {
                    ax += f0.x; ay += f0.y;
                }
            }
            float ni = g_norm_in[node];
            float vx = fmaxf(ax * ni + bc.x, 0.f);
            float vy = fmaxf(ay * ni + bc.y, 0.f);
            float s = g_norm_out[node];
            vx *= s; vy *= s;
            __half2 h = __float22half2_rn(make_float2(vx, vy));
            As[r * ALD + c] = *(uint32_t*)&h;
        }
    }
    __syncthreads();

    // ---- GEMM mainloop ----
    int warpRow = warp >> 2, warpCol = warp & 3;
    int gid = lane >> 2, tig = lane & 3;
    int aBase = warpRow * 64, bBase = warpCol * 32;

    float acc[4][4][4];
#pragma unroll
    for (int mf = 0; mf < 4; mf++)
#pragma unroll
        for (int nf = 0; nf < 4; nf++)
#pragma unroll
            for (int q = 0; q < 4; q++) acc[mf][nf][q] = 0.f;

#pragma unroll
    for (int ks = 0; ks < 8; ks++) {
        int kw = ks * 8;
        uint32_t bfr[4][2];
#pragma unroll
        for (int nf = 0; nf < 4; nf++) {
            int n = bBase + nf * 8 + gid;
            bfr[nf][0] = Ws[n * ALD + kw + tig];
            bfr[nf][1] = Ws[n * ALD + kw + 4 + tig];
        }
        uint32_t afr[4][4];
#pragma unroll
        for (int mf = 0; mf < 4; mf++) {
            int r = aBase + mf * 16 + gid;
            afr[mf][0] = As[r * ALD + kw + tig];
            afr[mf][1] = As[(r + 8) * ALD + kw + tig];
            afr[mf][2] = As[r * ALD + kw + 4 + tig];
            afr[mf][3] = As[(r + 8) * ALD + kw + 4 + tig];
        }
#pragma unroll
        for (int mf = 0; mf < 4; mf++)
#pragma unroll
            for (int nf = 0; nf < 4; nf++)
                MMA_H16(acc[mf][nf], afr[mf], bfr[nf]);
    }

#pragma unroll
    for (int mf = 0; mf < 4; mf++) {
        int r0 = rowBase + aBase + mf * 16 + gid;
        int r1 = r0 + 8;
#pragma unroll
        for (int nf = 0; nf < 4; nf++) {
            int h2col = ((bBase + nf * 8) >> 1) + tig;
            if (r0 < M)
                ((__half2*)out)[(size_t)r0 * 64 + h2col] =
                    __float22half2_rn(make_float2(acc[mf][nf][0], acc[mf][nf][1]));
            if (r1 < M)
                ((__half2*)out)[(size_t)r1 * 64 + h2col] =
                    __float22half2_rn(make_float2(acc[mf][nf][2], acc[mf][nf][3]));
        }
    }
}

// ---------------- fused aggregation + GEMM40 (layer-1 agg + W2 transform) ----------------
__global__ void __launch_bounds__(256)
fused_agg_gemm40(const uint32_t* __restrict__ gin,
                 const uint4* __restrict__ WT /* 40 rows */,
                 const float* __restrict__ bias,
                 uint32_t* __restrict__ out /* 20 half2 words/row */, int M) {
    extern __shared__ uint32_t sm[];
    uint32_t* As = sm;
    uint32_t* Ws = sm + 128 * ALD;  // [40][ALD]

    int tid = threadIdx.x, warp = tid >> 5, lane = tid & 31;
    int rowBase = blockIdx.x * 128;

    // copy W2^T (40 rows x 16 uint4 = 640)
#pragma unroll
    for (int it = 0; it < 3; it++) {
        int li = it * 256 + tid;
        if (li < 640) {
            int n = li >> 4;
            int q = li & 15;
            uint4 v = WT[n * 17 + q];
            uint32_t* p = Ws + n * ALD + q * 4;
            p[0] = v.x; p[1] = v.y; p[2] = v.z; p[3] = v.w;
        }
    }

    // ---- aggregation phase (EW=0, relu, pre-scale by norm_out) ----
    int c  = tid & 63;
    int ty = tid >> 6;
    float2 bc = *(const float2*)(bias + 2 * c);
#pragma unroll 1
    for (int rr = 0; rr < 32; rr++) {
        int r = ty * 32 + rr;
        int node = rowBase + r;
        if (node < M) {
            int beg = g_row_ptr[node];
            int end = g_row_ptr[node + 1];
            float ax = 0.f, ay = 0.f;
            int e = beg;
            for (; e + 3 < end; e += 4) {
                uint32_t u0 = gin[(size_t)g_col[e]     * 64 + c];
                uint32_t u1 = gin[(size_t)g_col[e + 1] * 64 + c];
                uint32_t u2 = gin[(size_t)g_col[e + 2] * 64 + c];
                uint32_t u3 = gin[(size_t)g_col[e + 3] * 64 + c];
                float2 f0 = __half22float2(*(__half2*)&u0);
                float2 f1 = __half22float2(*(__half2*)&u1);
                float2 f2 = __half22float2(*(__half2*)&u2);
                float2 f3 = __half22float2(*(__half2*)&u3);
                ax += f0.x + f1.x + f2.x + f3.x;
                ay += f0.y + f1.y + f2.y + f3.y;
            }
            for (; e < end; e++) {
                uint32_t u0 = gin[(size_t)g_col[e] * 64 + c];
                float2 f0 = __half22float2(*(__half2*)&u0);
                ax += f0.x; ay += f0.y;
            }
            float ni = g_norm_in[node];
            float vx = fmaxf(ax * ni + bc.x, 0.f);
            float vy = fmaxf(ay * ni + bc.y, 0.f);
            float s = g_norm_out[node];
            vx *= s; vy *= s;
            __half2 h = __float22half2_rn(make_float2(vx, vy));
            As[r * ALD + c] = *(uint32_t*)&h;
        }
    }
    __syncthreads();

    // ---- GEMM40 mainloop: each warp owns 16 rows x 40 cols ----
    int gid = lane >> 2, tig = lane & 3;
    int aBase = warp * 16;

    float acc[5][4];
#pragma unroll
    for (int nf = 0; nf < 5; nf++)
#pragma unroll
        for (int q = 0; q < 4; q++) acc[nf][q] = 0.f;

#pragma unroll
    for (int ks = 0; ks < 8; ks++) {
        int kw = ks * 8;
        uint32_t afr[4];
        {
            int r = aBase + gid;
            afr[0] = As[r * ALD + kw + tig];
            afr[1] = As[(r + 8) * ALD + kw + tig];
            afr[2] = As[r * ALD + kw + 4 + tig];
            afr[3] = As[(r + 8) * ALD + kw + 4 + tig];
        }
#pragma unroll
        for (int nf = 0; nf < 5; nf++) {
            int n = nf * 8 + gid;
            uint32_t bfr[2];
            bfr[0] = Ws[n * ALD + kw + tig];
            bfr[1] = Ws[n * ALD + kw + 4 + tig];
            MMA_H16(acc[nf], afr, bfr);
        }
    }

    int r0 = rowBase + aBase + gid;
    int r1 = r0 + 8;
#pragma unroll
    for (int nf = 0; nf < 5; nf++) {
        int h2col = nf * 4 + tig;
        if (r0 < M)
            ((__half2*)out)[(size_t)r0 * 20 + h2col] =
                __float22half2_rn(make_float2(acc[nf][0], acc[nf][1]));
        if (r1 < M)
            ((__half2*)out)[(size_t)r1 * 20 + h2col] =
                __float22half2_rn(make_float2(acc[nf][2], acc[nf][3]));
    }
}

// ---------------- final aggregation (40 cols, fp16 in, fp32 out) ----------------
#define AGG_BLOCKS 512
__global__ void __launch_bounds__(256)
agg40_kernel(const uint32_t* __restrict__ tin /* 20 half2 words/row */,
             const float* __restrict__ bias,
             float* __restrict__ out, int N) {
    int lane = threadIdx.x & 31;
    int warpId = blockIdx.x * 8 + (threadIdx.x >> 5);
    int totalWarps = gridDim.x * 8;
    if (lane >= 20) return;
    float2 b2 = *(const float2*)(bias + lane * 2);

    for (int node = warpId; node < N; node += totalWarps) {
        int beg = g_row_ptr[node];
        int end = g_row_ptr[node + 1];
        float ax = 0.f, ay = 0.f;
        int e = beg;
        for (; e + 3 < end; e += 4) {
            uint32_t u0 = tin[(size_t)g_col[e]     * 20 + lane];
            uint32_t u1 = tin[(size_t)g_col[e + 1] * 20 + lane];
            uint32_t u2 = tin[(size_t)g_col[e + 2] * 20 + lane];
            uint32_t u3 = tin[(size_t)g_col[e + 3] * 20 + lane];
            float2 f0 = __half22float2(*(__half2*)&u0);
            float2 f1 = __half22float2(*(__half2*)&u1);
            float2 f2 = __half22float2(*(__half2*)&u2);
            float2 f3 = __half22float2(*(__half2*)&u3);
            ax += f0.x + f1.x + f2.x + f3.x;
            ay += f0.y + f1.y + f2.y + f3.y;
        }
        for (; e < end; e++) {
            uint32_t u0 = tin[(size_t)g_col[e] * 20 + lane];
            float2 f0 = __half22float2(*(__half2*)&u0);
            ax += f0.x; ay += f0.y;
        }
        float ni = g_norm_in[node];
        *(float2*)(out + (size_t)node * CLS + lane * 2) =
            make_float2(ax * ni + b2.x, ay * ni + b2.y);
    }
}

// ---------------- host launcher ----------------
extern "C" void kernel_launch(void* const* d_in, const int* in_sizes, int n_in,
                              void* d_out, int out_size) {
    const float* features = (const float*)d_in[0];
    const int*   src      = (const int*)d_in[1];
    const int*   dst      = (const int*)d_in[2];
    const float* W0       = (const float*)d_in[3];
    const float* b0       = (const float*)d_in[4];
    const float* W1       = (const float*)d_in[5];
    const float* b1       = (const float*)d_in[6];
    const float* W2       = (const float*)d_in[7];
    const float* b2       = (const float*)d_in[8];
    float* out = (float*)d_out;

    int N = in_sizes[0] / KDIM;   // 50000
    int E = in_sizes[1];          // 800000

    static cudaStream_t s_pre = nullptr;
    static cudaEvent_t  ev_fork = nullptr, ev_join = nullptr;
    static void *p_buf_a = nullptr, *p_buf_b = nullptr;
    static void *p_wt0 = nullptr, *p_wt1 = nullptr, *p_wt2 = nullptr;
    if (!s_pre) {
        cudaStreamCreateWithFlags(&s_pre, cudaStreamNonBlocking);
        cudaEventCreateWithFlags(&ev_fork, cudaEventDisableTiming);
        cudaEventCreateWithFlags(&ev_join, cudaEventDisableTiming);
        cudaGetSymbolAddress(&p_buf_a, g_buf_a);
        cudaGetSymbolAddress(&p_buf_b, g_buf_b);
        cudaGetSymbolAddress(&p_wt0, g_wt0);
        cudaGetSymbolAddress(&p_wt1, g_wt1);
        cudaGetSymbolAddress(&p_wt2, g_wt2);
        cudaFuncSetAttribute(gemm0_kernel,
                             cudaFuncAttributeMaxDynamicSharedMemorySize, GEMM_SMEM);
        cudaFuncSetAttribute(fused_agg_gemm128<1>,
                             cudaFuncAttributeMaxDynamicSharedMemorySize, GEMM_SMEM);
        cudaFuncSetAttribute(fused_agg_gemm40,
                             cudaFuncAttributeMaxDynamicSharedMemorySize, GEMM40_SMEM);
    }

    int nScanBlocks = (N + 255) / 256;
    int gemmGrid = (N + 127) / 128;

    // ---- fork: graph preprocessing on s_pre; weight conversion + GEMM0 on main ----
    cudaEventRecord(ev_fork, 0);
    cudaStreamWaitEvent(s_pre, ev_fork, 0);

    init_zero_kernel<<<196, 256, 0, s_pre>>>(N);
    degree_kernel<<<(E + 255) / 256, 256, 0, s_pre>>>(src, dst, E);
    norm_partial_kernel<<<nScanBlocks, 256, 0, s_pre>>>(N);
    scan_offsets_kernel<<<1, 256, 0, s_pre>>>(nScanBlocks, N);
    fill_rowptr_kernel<<<nScanBlocks, 256, 0, s_pre>>>(N);
    csr_fill_kernel<<<(E + 255) / 256, 256, 0, s_pre>>>(src, dst, E);
    cudaEventRecord(ev_join, s_pre);

    wconvert128_kernel<<<32, 256>>>(W0, (uint32_t*)p_wt0);
    wconvert128_kernel<<<32, 256>>>(W1, (uint32_t*)p_wt1);
    wconvert40_kernel<<<10, 256>>>(W2, (uint32_t*)p_wt2);

    // layer 0 GEMM (independent of graph): features @ W0 -> buf_a (fp16)
    gemm0_kernel<<<gemmGrid, 256, GEMM_SMEM>>>(features, (const uint4*)p_wt0,
                                               (uint32_t*)p_buf_a, N);

    cudaStreamWaitEvent(0, ev_join, 0);

    // fused layer-0 agg (EW=1) + W1 transform -> buf_b (fp16)
    fused_agg_gemm128<1><<<gemmGrid, 256, GEMM_SMEM>>>(
        (const uint32_t*)p_buf_a, (const uint4*)p_wt1, b0, (uint32_t*)p_buf_b, N);

    // fused layer-1 agg (EW=0) + W2 transform -> buf_a (fp16 logits, 20 words/row)
    fused_agg_gemm40<<<gemmGrid, 256, GEMM40_SMEM>>>(
        (const uint32_t*)p_buf_b, (const uint4*)p_wt2, b1, (uint32_t*)p_buf_a, N);

    // final aggregation -> fp32 out
    agg40_kernel<<<AGG_BLOCKS, 256>>>((const uint32_t*)p_buf_a, b2, out, N);
}

// round 8
// speedup vs baseline: 1.5055x; 1.5055x over previous
#include <cuda_runtime.h>
#include <cuda_fp16.h>
#include <math.h>
#include <stdint.h>

#define NN 50000
#define EE 800000
#define KDIM 128
#define HID 128
#define CLS 40

#define ALD 68   // half2-words per smem row (64 data + 4 pad) -> conflict-free MMA frag loads

// ---------------- scratch (device globals; no allocation allowed) ----------------
__device__ int   g_deg_out[NN];
__device__ int   g_deg_in[NN];
__device__ int   g_cursor[NN];
__device__ int   g_row_ptr[NN + 1];
__device__ int   g_col[EE];
__device__ float g_norm_out[NN];
__device__ float g_norm_in[NN];
__device__ int   g_block_sums[256];
__device__ int   g_block_off[256];
__device__ __align__(16) uint32_t g_wt0[128 * ALD];   // W0^T fp16, n-major k-contig
__device__ __align__(16) uint32_t g_wt1[128 * ALD];   // W1^T
__device__ __align__(16) uint32_t g_wt2[40 * ALD];    // W2^T
__device__ __align__(16) float g_buf_a[(size_t)NN * 128];   // fp16 scratch
__device__ __align__(16) float g_buf_b[(size_t)NN * 128];   // fp16 scratch

// ---------------- graph preprocessing ----------------
__global__ void init_zero_kernel(int n) {
    for (int i = blockIdx.x * blockDim.x + threadIdx.x; i < n; i += gridDim.x * blockDim.x) {
        g_deg_out[i] = 0;
        g_deg_in[i]  = 0;
    }
}

__global__ void degree_kernel(const int* __restrict__ src, const int* __restrict__ dst, int E) {
    int e = blockIdx.x * blockDim.x + threadIdx.x;
    if (e < E) {
        atomicAdd(&g_deg_out[src[e]], 1);
        atomicAdd(&g_deg_in[dst[e]], 1);
    }
}

__global__ void norm_partial_kernel(int n) {
    __shared__ int sdata[8];
    int t = threadIdx.x;
    int i = blockIdx.x * 256 + t;
    int din = 0;
    if (i < n) {
        int dout = g_deg_out[i]; if (dout < 1) dout = 1;
        din = g_deg_in[i];
        int dc = (din < 1) ? 1 : din;
        g_norm_out[i] = rsqrtf((float)dout);
        g_norm_in[i]  = rsqrtf((float)dc);
    }
    int v = din;
    for (int off = 16; off > 0; off >>= 1)
        v += __shfl_down_sync(0xffffffff, v, off);
    if ((t & 31) == 0) sdata[t >> 5] = v;
    __syncthreads();
    if (t < 8) {
        int w = sdata[t];
        for (int off = 4; off > 0; off >>= 1)
            w += __shfl_down_sync(0xff, w, off);
        if (t == 0) g_block_sums[blockIdx.x] = w;
    }
}

__global__ void scan_offsets_kernel(int nblocks, int n) {
    __shared__ int s[256];
    int t = threadIdx.x;
    int v = (t < nblocks) ? g_block_sums[t] : 0;
    s[t] = v;
    __syncthreads();
    for (int off = 1; off < 256; off <<= 1) {
        int u = (t >= off) ? s[t - off] : 0;
        __syncthreads();
        s[t] += u;
        __syncthreads();
    }
    if (t < nblocks) g_block_off[t] = s[t] - v;
    if (t == nblocks - 1) g_row_ptr[n] = s[t];
}

__global__ void fill_rowptr_kernel(int n) {
    __shared__ int s[256];
    int t = threadIdx.x;
    int i = blockIdx.x * 256 + t;
    int v = (i < n) ? g_deg_in[i] : 0;
    s[t] = v;
    __syncthreads();
    for (int off = 1; off < 256; off <<= 1) {
        int u = (t >= off) ? s[t - off] : 0;
        __syncthreads();
        s[t] += u;
        __syncthreads();
    }
    if (i < n) {
        int rp = s[t] - v + g_block_off[blockIdx.x];
        g_row_ptr[i] = rp;
        g_cursor[i]  = rp;
    }
}

__global__ void csr_fill_kernel(const int* __restrict__ src, const int* __restrict__ dst, int E) {
    int e = blockIdx.x * blockDim.x + threadIdx.x;
    if (e < E) {
        int p = atomicAdd(&g_cursor[dst[e]], 1);
        g_col[p] = src[e];
    }
}

// ---------------- weight pre-conversion: W (KxN fp32 row-major) -> WT (n-major, k-contig fp16) ----------------
__global__ void wconvert128_kernel(const float* __restrict__ W, uint32_t* __restrict__ WT) {
    int li = blockIdx.x * 256 + threadIdx.x;   // 8192 tasks
    int n = li & 127;
    int j = li >> 7;                           // 0..63
    float lo = W[(size_t)(2 * j) * 128 + n];
    float hi = W[(size_t)(2 * j + 1) * 128 + n];
    __half2 h = __float22half2_rn(make_float2(lo, hi));
    WT[n * ALD + j] = *(uint32_t*)&h;
}

__global__ void wconvert40_kernel(const float* __restrict__ W, uint32_t* __restrict__ WT) {
    int li = blockIdx.x * 256 + threadIdx.x;   // 2560 tasks
    if (li >= 40 * 64) return;
    int n = li % 40;
    int j = li / 40;                           // 0..63
    float lo = W[(size_t)(2 * j) * CLS + n];
    float hi = W[(size_t)(2 * j + 1) * CLS + n];
    __half2 h = __float22half2_rn(make_float2(lo, hi));
    WT[n * ALD + j] = *(uint32_t*)&h;
}

// ---------------- MMA macro (fp16 inputs, fp32 accum) ----------------
#define MMA_H16(d, a, b)                                                     \
    asm volatile(                                                            \
        "mma.sync.aligned.m16n8k16.row.col.f32.f16.f16.f32 "                 \
        "{%0,%1,%2,%3}, {%4,%5,%6,%7}, {%8,%9}, {%0,%1,%2,%3};"              \
        : "+f"(d[0]), "+f"(d[1]), "+f"(d[2]), "+f"(d[3])                     \
        : "r"(a[0]), "r"(a[1]), "r"(a[2]), "r"(a[3]), "r"(b[0]), "r"(b[1]))

#define GEMM_SMEM  ((128 * ALD + 128 * ALD) * 4)
#define GEMM40_SMEM ((128 * ALD + 40 * ALD) * 4)

// ---------------- GEMM 128 out cols: A (fp32 or fp16) @ WT -> fp16 out ----------------
// AF32=1: A is fp32 (features); AF32=0: A is fp16 rows of 64 half2 words.
template <int AF32>
__global__ void __launch_bounds__(256)
gemm128_h16(const void* __restrict__ Ain, const uint4* __restrict__ WT /* 17 uint4/row */,
            uint32_t* __restrict__ out /* 64 half2 words/row */, int M) {
    extern __shared__ uint32_t sm[];
    uint32_t* As = sm;                 // [128][ALD]
    uint32_t* Ws = sm + 128 * ALD;     // [128][ALD]

    int tid = threadIdx.x, warp = tid >> 5, lane = tid & 31;
    int rowBase = blockIdx.x * 128;

    // copy preconverted W^T (128 rows x 16 uint4) — conflict-free
#pragma unroll
    for (int it = 0; it < 8; it++) {
        int li = it * 256 + tid;
        int n  = li >> 4;
        int q  = li & 15;
        uint4 v = WT[n * 17 + q];
        uint32_t* p = Ws + n * ALD + q * 4;
        p[0] = v.x; p[1] = v.y; p[2] = v.z; p[3] = v.w;
    }

    if (AF32) {
        const float* A = (const float*)Ain;
#pragma unroll
        for (int it = 0; it < 16; it++) {
            int li = it * 256 + tid;
            int r  = li >> 5;
            int c4 = (li & 31) << 2;
            float4 v = make_float4(0.f, 0.f, 0.f, 0.f);
            if (rowBase + r < M)
                v = *(const float4*)(A + (size_t)(rowBase + r) * 128 + c4);
            ((__half2*)As)[r * ALD + (c4 >> 1)]     = __float22half2_rn(make_float2(v.x, v.y));
            ((__half2*)As)[r * ALD + (c4 >> 1) + 1] = __float22half2_rn(make_float2(v.z, v.w));
        }
    } else {
        const uint4* A = (const uint4*)Ain;     // 16 uint4 per row
#pragma unroll
        for (int it = 0; it < 8; it++) {
            int li = it * 256 + tid;
            int r  = li >> 4;
            int w4 = (li & 15) << 2;
            uint4 v = make_uint4(0u, 0u, 0u, 0u);
            if (rowBase + r < M)
                v = A[(size_t)(rowBase + r) * 16 + (w4 >> 2)];
            As[r * ALD + w4]     = v.x;
            As[r * ALD + w4 + 1] = v.y;
            As[r * ALD + w4 + 2] = v.z;
            As[r * ALD + w4 + 3] = v.w;
        }
    }
    __syncthreads();

    int warpRow = warp >> 2, warpCol = warp & 3;
    int gid = lane >> 2, tig = lane & 3;
    int aBase = warpRow * 64, bBase = warpCol * 32;

    float acc[4][4][4];
#pragma unroll
    for (int mf = 0; mf < 4; mf++)
#pragma unroll
        for (int nf = 0; nf < 4; nf++)
#pragma unroll
            for (int q = 0; q < 4; q++) acc[mf][nf][q] = 0.f;

#pragma unroll
    for (int ks = 0; ks < 8; ks++) {
        int kw = ks * 8;
        uint32_t bfr[4][2];
#pragma unroll
        for (int nf = 0; nf < 4; nf++) {
            int n = bBase + nf * 8 + gid;
            bfr[nf][0] = Ws[n * ALD + kw + tig];
            bfr[nf][1] = Ws[n * ALD + kw + 4 + tig];
        }
        uint32_t afr[4][4];
#pragma unroll
        for (int mf = 0; mf < 4; mf++) {
            int r = aBase + mf * 16 + gid;
            afr[mf][0] = As[r * ALD + kw + tig];
            afr[mf][1] = As[(r + 8) * ALD + kw + tig];
            afr[mf][2] = As[r * ALD + kw + 4 + tig];
            afr[mf][3] = As[(r + 8) * ALD + kw + 4 + tig];
        }
#pragma unroll
        for (int mf = 0; mf < 4; mf++)
#pragma unroll
            for (int nf = 0; nf < 4; nf++)
                MMA_H16(acc[mf][nf], afr[mf], bfr[nf]);
    }

#pragma unroll
    for (int mf = 0; mf < 4; mf++) {
        int r0 = rowBase + aBase + mf * 16 + gid;
        int r1 = r0 + 8;
#pragma unroll
        for (int nf = 0; nf < 4; nf++) {
            int h2col = ((bBase + nf * 8) >> 1) + tig;
            if (r0 < M)
                ((__half2*)out)[(size_t)r0 * 64 + h2col] =
                    __float22half2_rn(make_float2(acc[mf][nf][0], acc[mf][nf][1]));
            if (r1 < M)
                ((__half2*)out)[(size_t)r1 * 64 + h2col] =
                    __float22half2_rn(make_float2(acc[mf][nf][2], acc[mf][nf][3]));
        }
    }
}

// ---------------- GEMM 40 out cols (A fp16, out fp16 20 words/row) ----------------
__global__ void __launch_bounds__(256)
gemm40_h16(const void* __restrict__ Ain, const uint4* __restrict__ WT /* 40 rows */,
           uint32_t* __restrict__ out, int M) {
    extern __shared__ uint32_t sm[];
    uint32_t* As = sm;                 // [128][ALD]
    uint32_t* Ws = sm + 128 * ALD;     // [40][ALD]

    int tid = threadIdx.x, warp = tid >> 5, lane = tid & 31;
    int rowBase = blockIdx.x * 128;

    // copy W2^T (40 rows x 16 uint4 = 640)
#pragma unroll
    for (int it = 0; it < 3; it++) {
        int li = it * 256 + tid;
        if (li < 640) {
            int n = li >> 4;
            int q = li & 15;
            uint4 v = WT[n * 17 + q];
            uint32_t* p = Ws + n * ALD + q * 4;
            p[0] = v.x; p[1] = v.y; p[2] = v.z; p[3] = v.w;
        }
    }

    const uint4* A = (const uint4*)Ain;
#pragma unroll
    for (int it = 0; it < 8; it++) {
        int li = it * 256 + tid;
        int r  = li >> 4;
        int w4 = (li & 15) << 2;
        uint4 v = make_uint4(0u, 0u, 0u, 0u);
        if (rowBase + r < M)
            v = A[(size_t)(rowBase + r) * 16 + (w4 >> 2)];
        As[r * ALD + w4]     = v.x;
        As[r * ALD + w4 + 1] = v.y;
        As[r * ALD + w4 + 2] = v.z;
        As[r * ALD + w4 + 3] = v.w;
    }
    __syncthreads();

    int gid = lane >> 2, tig = lane & 3;
    int aBase = warp * 16;

    float acc[5][4];
#pragma unroll
    for (int nf = 0; nf < 5; nf++)
#pragma unroll
        for (int q = 0; q < 4; q++) acc[nf][q] = 0.f;

#pragma unroll
    for (int ks = 0; ks < 8; ks++) {
        int kw = ks * 8;
        uint32_t afr[4];
        {
            int r = aBase + gid;
            afr[0] = As[r * ALD + kw + tig];
            afr[1] = As[(r + 8) * ALD + kw + tig];
            afr[2] = As[r * ALD + kw + 4 + tig];
            afr[3] = As[(r + 8) * ALD + kw + 4 + tig];
        }
#pragma unroll
        for (int nf = 0; nf < 5; nf++) {
            int n = nf * 8 + gid;
            uint32_t bfr[2];
            bfr[0] = Ws[n * ALD + kw + tig];
            bfr[1] = Ws[n * ALD + kw + 4 + tig];
            MMA_H16(acc[nf], afr, bfr);
        }
    }

    int r0 = rowBase + aBase + gid;
    int r1 = r0 + 8;
#pragma unroll
    for (int nf = 0; nf < 5; nf++) {
        int h2col = nf * 4 + tig;
        if (r0 < M)
            ((__half2*)out)[(size_t)r0 * 20 + h2col] =
                __float22half2_rn(make_float2(acc[nf][0], acc[nf][1]));
        if (r1 < M)
            ((__half2*)out)[(size_t)r1 * 20 + h2col] =
                __float22half2_rn(make_float2(acc[nf][2], acc[nf][3]));
    }
}

// ---------------- aggregation (128 cols, fp16 in, fp16 out), warp-per-node persistent ----
#define AGG_BLOCKS 512
template <int RELU, int EW, int OS>
__global__ void __launch_bounds__(256)
agg_f16_kernel(const uint2* __restrict__ tin /* rows of 32 uint2 */,
               const float* __restrict__ bias,
               uint2* __restrict__ outh /* rows of 32 uint2 */, int N) {
    int lane = threadIdx.x & 31;
    int warpId = blockIdx.x * 8 + (threadIdx.x >> 5);
    int totalWarps = gridDim.x * 8;
    float4 b4 = *(const float4*)(bias + lane * 4);

    for (int node = warpId; node < N; node += totalWarps) {
        int beg = g_row_ptr[node];
        int end = g_row_ptr[node + 1];
        float a0 = 0.f, a1 = 0.f, a2 = 0.f, a3 = 0.f;
        int e = beg;
        for (; e + 3 < end; e += 4) {
            int s0 = g_col[e], s1 = g_col[e + 1], s2 = g_col[e + 2], s3 = g_col[e + 3];
            uint2 u0 = tin[(size_t)s0 * 32 + lane];
            uint2 u1 = tin[(size_t)s1 * 32 + lane];
            uint2 u2 = tin[(size_t)s2 * 32 + lane];
            uint2 u3 = tin[(size_t)s3 * 32 + lane];
            float2 p0 = __half22float2(*(__half2*)&u0.x), q0 = __half22float2(*(__half2*)&u0.y);
            float2 p1 = __half22float2(*(__half2*)&u1.x), q1 = __half22float2(*(__half2*)&u1.y);
            float2 p2 = __half22float2(*(__half2*)&u2.x), q2 = __half22float2(*(__half2*)&u2.y);
            float2 p3 = __half22float2(*(__half2*)&u3.x), q3 = __half22float2(*(__half2*)&u3.y);
            if (EW) {
                float w0 = g_norm_out[s0], w1 = g_norm_out[s1];
                float w2 = g_norm_out[s2], w3 = g_norm_out[s3];
                a0 = fmaf(p0.x, w0, a0); a1 = fmaf(p0.y, w0, a1);
                a2 = fmaf(q0.x, w0, a2); a3 = fmaf(q0.y, w0, a3);
                a0 = fmaf(p1.x, w1, a0); a1 = fmaf(p1.y, w1, a1);
                a2 = fmaf(q1.x, w1, a2); a3 = fmaf(q1.y, w1, a3);
                a0 = fmaf(p2.x, w2, a0); a1 = fmaf(p2.y, w2, a1);
                a2 = fmaf(q2.x, w2, a2); a3 = fmaf(q2.y, w2, a3);
                a0 = fmaf(p3.x, w3, a0); a1 = fmaf(p3.y, w3, a1);
                a2 = fmaf(q3.x, w3, a2); a3 = fmaf(q3.y, w3, a3);
            } else {
                a0 += p0.x + p1.x + p2.x + p3.x;
                a1 += p0.y + p1.y + p2.y + p3.y;
                a2 += q0.x + q1.x + q2.x + q3.x;
                a3 += q0.y + q1.y + q2.y + q3.y;
            }
        }
        for (; e < end; e++) {
            int s0 = g_col[e];
            uint2 u0 = tin[(size_t)s0 * 32 + lane];
            float2 p0 = __half22float2(*(__half2*)&u0.x), q0 = __half22float2(*(__half2*)&u0.y);
            if (EW) {
                float w0 = g_norm_out[s0];
                a0 = fmaf(p0.x, w0, a0); a1 = fmaf(p0.y, w0, a1);
                a2 = fmaf(q0.x, w0, a2); a3 = fmaf(q0.y, w0, a3);
            } else {
                a0 += p0.x; a1 += p0.y; a2 += q0.x; a3 += q0.y;
            }
        }
        float ni = g_norm_in[node];
        float v0 = a0 * ni + b4.x;
        float v1 = a1 * ni + b4.y;
        float v2 = a2 * ni + b4.z;
        float v3 = a3 * ni + b4.w;
        if (RELU) {
            v0 = fmaxf(v0, 0.f); v1 = fmaxf(v1, 0.f);
            v2 = fmaxf(v2, 0.f); v3 = fmaxf(v3, 0.f);
        }
        if (OS) {
            float s = g_norm_out[node];
            v0 *= s; v1 *= s; v2 *= s; v3 *= s;
        }
        uint2 w;
        *(__half2*)&w.x = __float22half2_rn(make_float2(v0, v1));
        *(__half2*)&w.y = __float22half2_rn(make_float2(v2, v3));
        outh[(size_t)node * 32 + lane] = w;
    }
}

// ---------------- final aggregation (40 cols, fp16 in, fp32 out) ----------------
__global__ void __launch_bounds__(256)
agg40_kernel(const uint32_t* __restrict__ tin /* rows of 20 half2 */,
             const float* __restrict__ bias,
             float* __restrict__ out, int N) {
    int lane = threadIdx.x & 31;
    int warpId = blockIdx.x * 8 + (threadIdx.x >> 5);
    int totalWarps = gridDim.x * 8;
    if (lane >= 20) return;
    float2 b2 = *(const float2*)(bias + lane * 2);

    for (int node = warpId; node < N; node += totalWarps) {
        int beg = g_row_ptr[node];
        int end = g_row_ptr[node + 1];
        float ax = 0.f, ay = 0.f;
        int e = beg;
        for (; e + 3 < end; e += 4) {
            uint32_t u0 = tin[(size_t)g_col[e]     * 20 + lane];
            uint32_t u1 = tin[(size_t)g_col[e + 1] * 20 + lane];
            uint32_t u2 = tin[(size_t)g_col[e + 2] * 20 + lane];
            uint32_t u3 = tin[(size_t)g_col[e + 3] * 20 + lane];
            float2 f0 = __half22float2(*(__half2*)&u0);
            float2 f1 = __half22float2(*(__half2*)&u1);
            float2 f2 = __half22float2(*(__half2*)&u2);
            float2 f3 = __half22float2(*(__half2*)&u3);
            ax += f0.x + f1.x + f2.x + f3.x;
            ay += f0.y + f1.y + f2.y + f3.y;
        }
        for (; e < end; e++) {
            uint32_t u0 = tin[(size_t)g_col[e] * 20 + lane];
            float2 f0 = __half22float2(*(__half2*)&u0);
            ax += f0.x; ay += f0.y;
        }
        float ni = g_norm_in[node];
        *(float2*)(out + (size_t)node * CLS + lane * 2) =
            make_float2(ax * ni + b2.x, ay * ni + b2.y);
    }
}

// ---------------- host launcher ----------------
extern "C" void kernel_launch(void* const* d_in, const int* in_sizes, int n_in,
                              void* d_out, int out_size) {
    const float* features = (const float*)d_in[0];
    const int*   src      = (const int*)d_in[1];
    const int*   dst      = (const int*)d_in[2];
    const float* W0       = (const float*)d_in[3];
    const float* b0       = (const float*)d_in[4];
    const float* W1       = (const float*)d_in[5];
    const float* b1       = (const float*)d_in[6];
    const float* W2       = (const float*)d_in[7];
    const float* b2       = (const float*)d_in[8];
    float* out = (float*)d_out;

    int N = in_sizes[0] / KDIM;   // 50000
    int E = in_sizes[1];          // 800000

    static cudaStream_t s_pre = nullptr;
    static cudaEvent_t  ev_fork = nullptr, ev_join = nullptr;
    static void *p_buf_a = nullptr, *p_buf_b = nullptr;
    static void *p_wt0 = nullptr, *p_wt1 = nullptr, *p_wt2 = nullptr;
    if (!s_pre) {
        cudaStreamCreateWithFlags(&s_pre, cudaStreamNonBlocking);
        cudaEventCreateWithFlags(&ev_fork, cudaEventDisableTiming);
        cudaEventCreateWithFlags(&ev_join, cudaEventDisableTiming);
        cudaGetSymbolAddress(&p_buf_a, g_buf_a);
        cudaGetSymbolAddress(&p_buf_b, g_buf_b);
        cudaGetSymbolAddress(&p_wt0, g_wt0);
        cudaGetSymbolAddress(&p_wt1, g_wt1);
        cudaGetSymbolAddress(&p_wt2, g_wt2);
        cudaFuncSetAttribute(gemm128_h16<1>,
                             cudaFuncAttributeMaxDynamicSharedMemorySize, GEMM_SMEM);
        cudaFuncSetAttribute(gemm128_h16<0>,
                             cudaFuncAttributeMaxDynamicSharedMemorySize, GEMM_SMEM);
        cudaFuncSetAttribute(gemm40_h16,
                             cudaFuncAttributeMaxDynamicSharedMemorySize, GEMM40_SMEM);
    }

    int nScanBlocks = (N + 255) / 256;
    int gemmGrid = (N + 127) / 128;

    // ---- fork: graph preprocessing on s_pre; weight conversion + GEMM0 on main ----
    cudaEventRecord(ev_fork, 0);
    cudaStreamWaitEvent(s_pre, ev_fork, 0);

    init_zero_kernel<<<196, 256, 0, s_pre>>>(N);
    degree_kernel<<<(E + 255) / 256, 256, 0, s_pre>>>(src, dst, E);
    norm_partial_kernel<<<nScanBlocks, 256, 0, s_pre>>>(N);
    scan_offsets_kernel<<<1, 256, 0, s_pre>>>(nScanBlocks, N);
    fill_rowptr_kernel<<<nScanBlocks, 256, 0, s_pre>>>(N);
    csr_fill_kernel<<<(E + 255) / 256, 256, 0, s_pre>>>(src, dst, E);
    cudaEventRecord(ev_join, s_pre);

    // weight preconversion (graph-independent, main stream)
    wconvert128_kernel<<<32, 256>>>(W0, (uint32_t*)p_wt0);
    wconvert128_kernel<<<32, 256>>>(W1, (uint32_t*)p_wt1);
    wconvert40_kernel<<<10, 256>>>(W2, (uint32_t*)p_wt2);

    // layer 0 GEMM (graph-independent): features @ W0 -> buf_a (fp16)
    gemm128_h16<1><<<gemmGrid, 256, GEMM_SMEM>>>(features, (const uint4*)p_wt0,
                                                 (uint32_t*)p_buf_a, N);

    cudaStreamWaitEvent(0, ev_join, 0);

    // layer 0 agg: edge-weighted, relu, pre-scale for next gemm; fp16 h out
    agg_f16_kernel<1, 1, 1><<<AGG_BLOCKS, 256>>>((const uint2*)p_buf_a, b0,
                                                 (uint2*)p_buf_b, N);
    // layer 1
    gemm128_h16<0><<<gemmGrid, 256, GEMM_SMEM>>>(p_buf_b, (const uint4*)p_wt1,
                                                 (uint32_t*)p_buf_a, N);
    agg_f16_kernel<1, 0, 1><<<AGG_BLOCKS, 256>>>((const uint2*)p_buf_a, b1,
                                                 (uint2*)p_buf_b, N);
    // layer 2 (40 classes)
    gemm40_h16<<<gemmGrid, 256, GEMM40_SMEM>>>(p_buf_b, (const uint4*)p_wt2,
                                               (uint32_t*)p_buf_a, N);
    agg40_kernel<<<AGG_BLOCKS, 256>>>((const uint32_t*)p_buf_a, b2, out, N);
}